// round 1
// baseline (speedup 1.0000x reference)
#include <cuda_runtime.h>
#include <math.h>

#define MAXN   65536
#define MAXL1  512
#define MAXV   512
#define MAXL2  16384

// ---------------- scratch (static device memory; no allocations) ----------------
__device__ int                g_counts[MAXN];
__device__ int                g_flag[MAXN];        // 0 = not in V, else slot+1
__device__ unsigned long long g_bestKey;
__device__ int                g_numL1, g_numV, g_numL2;
__device__ int                g_L1[MAXL1];
__device__ int                g_L2[MAXL2];
__device__ float              g_nodeMid[MAXV * 80];
__device__ float              g_w3j[675];

// path tables: TP2_PATHS = [(0,2),(1,1),(1,3),(2,0),(2,2),(3,1),(3,3)], l3 = 2
__device__ const int c_pl1[7]    = {0, 1, 1, 2, 2, 3, 3};
__device__ const int c_pl2[7]    = {2, 1, 3, 0, 2, 1, 3};
__device__ const int c_w3joff[7] = {0, 25, 70, 175, 200, 325, 430};
__device__ const int c_off[4]    = {0, 5, 20, 45};   // mid block offsets
__device__ const int c_shoff[4]  = {0, 1, 4, 9};     // sh block offsets

// ---------------- constants ----------------
#define INV_SQRT20  0.2236067977499790f
#define INV_SQRT30  0.1825741858350554f
#define INV_SQRT6   0.4082482904638630f
#define NORM2MOM    1.679177f
#define ALPHA2      0.3779644730092272f   // sqrt(5/35)
#define EMB_SCALE   8.4335731381317640f   // 1.14136 * e^2

// ---------------- Wigner 3j computed on-device (double) ----------------
__device__ __forceinline__ double dfact(int n) {
    const double F[13] = {1., 1., 2., 6., 24., 120., 720., 5040., 40320.,
                          362880., 3628800., 39916800., 479001600.};
    return F[n];
}

__device__ double su2_cg(int j1, int m1, int j2, int m2, int j3, int m3) {
    if (m3 != m1 + m2) return 0.0;
    int vmin = max(max(-j1 + j2 + m3, -j1 + m1), 0);
    int vmax = min(min(j2 + j3 + m1, j3 - j1 + j2), j3 + m3);
    double C = sqrt((2.0 * j3 + 1.0) * dfact(j3 + j1 - j2) * dfact(j3 - j1 + j2) *
                    dfact(j1 + j2 - j3) * dfact(j3 + m3) * dfact(j3 - m3) /
                    (dfact(j1 + j2 + j3 + 1) * dfact(j1 - m1) * dfact(j1 + m1) *
                     dfact(j2 - m2) * dfact(j2 + m2)));
    double S = 0.0;
    for (int v = vmin; v <= vmax; v++) {
        double sgn = ((v + j2 + m2) & 1) ? -1.0 : 1.0;
        S += sgn / dfact(v) * dfact(j2 + j3 + m1 - v) * dfact(j1 - m1 + v) /
             dfact(j3 - j1 + j2 - v) / dfact(j3 + m3 - v) / dfact(v + j1 - j2 - m3);
    }
    return C * S;
}

// real basis change q (row-major 7x7, only (2l+1)^2 used)
__device__ void build_Q(int l, double2* Q) {
    for (int i = 0; i < 49; i++) Q[i] = make_double2(0.0, 0.0);
    const double inv = 0.70710678118654752440;
    for (int m = -l; m < 0; m++) {
        Q[(l + m) * 7 + (l - m)] = make_double2(inv, 0.0);
        Q[(l + m) * 7 + (l + m)] = make_double2(0.0, -inv);
    }
    Q[l * 7 + l] = make_double2(1.0, 0.0);
    for (int m = 1; m <= l; m++) {
        double sgn = (m & 1) ? -1.0 : 1.0;
        Q[(l + m) * 7 + (l + m)] = make_double2(sgn * inv, 0.0);
        Q[(l + m) * 7 + (l - m)] = make_double2(0.0, sgn * inv);
    }
    // multiply by (-i)^l
    double pr, pi;
    switch (l & 3) {
        case 0: pr = 1;  pi = 0;  break;
        case 1: pr = 0;  pi = -1; break;
        case 2: pr = -1; pi = 0;  break;
        default: pr = 0; pi = 1;  break;
    }
    for (int i = 0; i < 49; i++) {
        double re = Q[i].x * pr - Q[i].y * pi;
        double im = Q[i].x * pi + Q[i].y * pr;
        Q[i] = make_double2(re, im);
    }
}

// one block per path
__global__ void k_w3j() {
    int p = blockIdx.x;
    int l1 = c_pl1[p], l2 = c_pl2[p];
    const int l3 = 2;
    int n1 = 2 * l1 + 1, n2 = 2 * l2 + 1;
    int tot = n1 * n2 * 5;

    __shared__ double2 Q1[49], Q2[49], Q3[49];
    __shared__ double  C[245];
    __shared__ double  Cr[245];
    __shared__ double  s_inorm;
    int tid = threadIdx.x;

    if (tid == 0) { build_Q(l1, Q1); build_Q(l2, Q2); build_Q(2, Q3); }
    for (int t = tid; t < tot; t += blockDim.x) {
        int i = t / (n2 * 5), r = t % (n2 * 5), k = r / 5, n = r % 5;
        int m1 = i - l1, m2 = k - l2;
        double v = 0.0;
        if (n == l3 + m1 + m2 && abs(m1 + m2) <= l3)
            v = su2_cg(l1, m1, l2, m2, l3, m1 + m2);
        C[t] = v;
    }
    __syncthreads();

    for (int t = tid; t < tot; t += blockDim.x) {
        int j = t / (n2 * 5), r = t % (n2 * 5), lc = r / 5, m = r % 5;
        double sre = 0.0;
        for (int i2 = 0; i2 < n1; i2++) {
            double2 qa = Q1[i2 * 7 + j];
            if (qa.x == 0.0 && qa.y == 0.0) continue;
            for (int k2 = 0; k2 < n2; k2++) {
                int n = 2 + (i2 - l1) + (k2 - l2);
                if (n < 0 || n > 4) continue;
                double c = C[(i2 * n2 + k2) * 5 + n];
                if (c == 0.0) continue;
                double2 qb = Q2[k2 * 7 + lc];
                double qr = qa.x * qb.x - qa.y * qb.y;
                double qi = qa.x * qb.y + qa.y * qb.x;
                double2 qg = Q3[n * 7 + m];   // conj applied below
                sre += c * (qr * qg.x + qi * qg.y);
            }
        }
        Cr[t] = sre;
    }
    __syncthreads();
    if (tid == 0) {
        double s = 0.0;
        for (int t = 0; t < tot; t++) s += Cr[t] * Cr[t];
        s_inorm = rsqrt(s);
    }
    __syncthreads();
    for (int t = tid; t < tot; t += blockDim.x)
        g_w3j[c_w3joff[p] + t] = (float)(Cr[t] * s_inorm);
}

// ---------------- small kernels ----------------
__global__ void k_init(int N) {
    int i = blockIdx.x * blockDim.x + threadIdx.x;
    int stride = gridDim.x * blockDim.x;
    for (int t = i; t < N; t += stride) { g_counts[t] = 0; g_flag[t] = 0; }
    for (int t = i; t < MAXV * 80; t += stride) g_nodeMid[t] = 0.0f;
    if (i == 0) { g_bestKey = 0ull; g_numL1 = 0; g_numV = 0; g_numL2 = 0; }
}

__global__ void k_bincount(const int* __restrict__ et, int E) {
    int e = blockIdx.x * blockDim.x + threadIdx.x;
    if (e < E) atomicAdd(&g_counts[et[e]], 1);
}

// argmax with first-index tiebreak: key = (count<<32) | (0xFFFFFFFF - idx)
__global__ void k_argmax(int N) {
    __shared__ unsigned long long s[256];
    int i = blockIdx.x * blockDim.x + threadIdx.x;
    unsigned long long key = 0ull;
    if (i < N)
        key = ((unsigned long long)(unsigned)g_counts[i] << 32) |
              (unsigned long long)(0xFFFFFFFFu - (unsigned)i);
    s[threadIdx.x] = key;
    __syncthreads();
    for (int off = 128; off > 0; off >>= 1) {
        if (threadIdx.x < off) {
            unsigned long long o = s[threadIdx.x + off];
            if (o > s[threadIdx.x]) s[threadIdx.x] = o;
        }
        __syncthreads();
    }
    if (threadIdx.x == 0) atomicMax(&g_bestKey, s[0]);
}

__global__ void k_findCo(const int* __restrict__ ef, const int* __restrict__ et, int E) {
    int co = (int)(0xFFFFFFFFu - (unsigned)(g_bestKey & 0xFFFFFFFFull));
    int e = blockIdx.x * blockDim.x + threadIdx.x;
    if (e < E && ef[e] == co) {
        int idx = atomicAdd(&g_numL1, 1);
        if (idx < MAXL1) g_L1[idx] = e;
        int v = et[e];
        int old = atomicCAS(&g_flag[v], 0, INT_MIN);
        if (old == 0) {
            int s = atomicAdd(&g_numV, 1);
            if (s < MAXV) atomicExch(&g_flag[v], s + 1);
        }
    }
}

__global__ void k_findV(const int* __restrict__ ef, int E) {
    int e = blockIdx.x * blockDim.x + threadIdx.x;
    if (e < E && g_flag[ef[e]] > 0) {
        int idx = atomicAdd(&g_numL2, 1);
        if (idx < MAXL2) g_L2[idx] = e;
    }
}

// ---------------- per-edge math ----------------
__device__ __forceinline__ void sh16(float x, float y, float z, float* sh) {
    float x2 = x * x, y2 = y * y, z2 = z * z;
    sh[0]  = 1.0f;
    sh[1]  = 1.7320508075688772f * x;
    sh[2]  = 1.7320508075688772f * y;
    sh[3]  = 1.7320508075688772f * z;
    sh[4]  = 3.8729833462074170f * x * z;
    sh[5]  = 3.8729833462074170f * x * y;
    sh[6]  = 2.2360679774997896f * (y2 - 0.5f * (x2 + z2));
    sh[7]  = 3.8729833462074170f * y * z;
    sh[8]  = 0.5f * 3.8729833462074170f * (z2 - x2);
    sh[9]  = 2.0916500663351889f * x * (3.0f * z2 - x2);
    sh[10] = 10.246950765959598f * x * y * z;
    sh[11] = 1.6201851746019651f * x * (5.0f * y2 - 1.0f);
    sh[12] = 1.3228756555322954f * y * (5.0f * y2 - 3.0f);
    sh[13] = 1.6201851746019651f * z * (5.0f * y2 - 1.0f);
    sh[14] = 5.1234753829797990f * y * (z2 - x2);
    sh[15] = 2.0916500663351889f * z * (z2 - 3.0f * x2);
}

__device__ __forceinline__ float ufun(float t) {
    return (t > 0.0f) ? expf(-1.0f / t) : 0.0f;
}

// compute mid for ~150 edges in L2 and scatter into g_nodeMid
__global__ void k_mids(const float* __restrict__ x, const float* __restrict__ pos,
                       const int* __restrict__ ef, const int* __restrict__ et,
                       const float* __restrict__ W1, const float* __restrict__ W2) {
    int n = min(g_numL2, MAXL2);
    for (int t = blockIdx.x * blockDim.x + threadIdx.x; t < n; t += gridDim.x * blockDim.x) {
        int e = g_L2[t];
        int a = ef[e], b = et[e];
        float dx = pos[3 * b + 0] - pos[3 * a + 0];
        float dy = pos[3 * b + 1] - pos[3 * a + 1];
        float dz = pos[3 * b + 2] - pos[3 * a + 2];
        float dist = sqrtf(dx * dx + dy * dy + dz * dz);
        float inv = 1.0f / dist;
        float sh[16];
        sh16(dx * inv, dy * inv, dz * inv, sh);

        // soft one-hot: diff_i = 6*d - (i+1)
        float emb[20];
        float d6 = dist * 6.0f;
        #pragma unroll
        for (int i = 0; i < 20; i++) {
            float diff = d6 - (float)(i + 1);
            emb[i] = EMB_SCALE * ufun(diff + 1.0f) * ufun(1.0f - diff);
        }
        // h = NORM2MOM * silu(emb @ W1 / sqrt(20))
        float h[30];
        #pragma unroll 5
        for (int j = 0; j < 30; j++) {
            float z = 0.0f;
            #pragma unroll
            for (int i = 0; i < 20; i++) z += emb[i] * W1[i * 30 + j];
            z *= INV_SQRT20;
            h[j] = NORM2MOM * z / (1.0f + expf(-z));
        }
        // tp_w = h @ W2 / sqrt(30)
        float tpw[20];
        #pragma unroll 5
        for (int k = 0; k < 20; k++) {
            float z = 0.0f;
            #pragma unroll
            for (int j = 0; j < 30; j++) z += h[j] * W2[j * 20 + k];
            tpw[k] = z * INV_SQRT30;
        }
        float s = x[b];
        int slot = g_flag[a] - 1;
        float* nm = g_nodeMid + slot * 80;
        // mid[off_l + u*(2l+1) + i] = s * tpw[l*5+u] * sh[shoff_l + i]
        #pragma unroll
        for (int u = 0; u < 5; u++)
            atomicAdd(&nm[u], s * tpw[u] * sh[0]);
        #pragma unroll
        for (int u = 0; u < 5; u++)
            for (int i = 0; i < 3; i++)
                atomicAdd(&nm[5 + u * 3 + i], s * tpw[5 + u] * sh[1 + i]);
        #pragma unroll
        for (int u = 0; u < 5; u++)
            for (int i = 0; i < 5; i++)
                atomicAdd(&nm[20 + u * 5 + i], s * tpw[10 + u] * sh[4 + i]);
        #pragma unroll
        for (int u = 0; u < 5; u++)
            for (int i = 0; i < 7; i++)
                atomicAdd(&nm[45 + u * 7 + i], s * tpw[15 + u] * sh[9 + i]);
    }
}

// second tensor product over Co's edges, reduce to 5 outputs
__global__ void k_final(const float* __restrict__ pos,
                        const int* __restrict__ ef, const int* __restrict__ et,
                        const float* __restrict__ tp2, float* __restrict__ out) {
    __shared__ float acc[5];
    if (threadIdx.x < 5) acc[threadIdx.x] = 0.0f;
    __syncthreads();

    int n = min(g_numL1, MAXL1);
    float o[5] = {0.f, 0.f, 0.f, 0.f, 0.f};
    for (int t = threadIdx.x; t < n; t += blockDim.x) {
        int e = g_L1[t];
        int a = ef[e], b = et[e];
        float dx = pos[3 * b + 0] - pos[3 * a + 0];
        float dy = pos[3 * b + 1] - pos[3 * a + 1];
        float dz = pos[3 * b + 2] - pos[3 * a + 2];
        float inv = rsqrtf(dx * dx + dy * dy + dz * dz);
        float sh[16];
        sh16(dx * inv, dy * inv, dz * inv, sh);

        int slot = g_flag[b] - 1;
        float m[80];
        const float* nm = g_nodeMid + slot * 80;
        #pragma unroll
        for (int i = 0; i < 80; i++) m[i] = nm[i] * INV_SQRT6;

        for (int p = 0; p < 7; p++) {
            int l1 = c_pl1[p], l2 = c_pl2[p];
            int n1 = 2 * l1 + 1, n2 = 2 * l2 + 1;
            float av[7];
            for (int i = 0; i < n1; i++) {
                float sacc = 0.0f;
                for (int u = 0; u < 5; u++)
                    sacc += tp2[p * 5 + u] * m[c_off[l1] + u * n1 + i];
                av[i] = sacc;
            }
            const float* W = g_w3j + c_w3joff[p];
            for (int i = 0; i < n1; i++)
                for (int j = 0; j < n2; j++) {
                    float cij = av[i] * sh[c_shoff[l2] + j];
                    for (int k = 0; k < 5; k++)
                        o[k] += W[(i * n2 + j) * 5 + k] * cij;
                }
        }
    }
    #pragma unroll
    for (int k = 0; k < 5; k++) atomicAdd(&acc[k], o[k] * ALPHA2);
    __syncthreads();
    if (threadIdx.x < 5) out[threadIdx.x] = acc[threadIdx.x] * INV_SQRT6;
}

// ---------------- launch ----------------
extern "C" void kernel_launch(void* const* d_in, const int* in_sizes, int n_in,
                              void* d_out, int out_size) {
    const float* x   = (const float*)d_in[0];
    const float* pos = (const float*)d_in[1];
    const int*   ef  = (const int*)d_in[2];
    const int*   et  = (const int*)d_in[3];
    const float* W1  = (const float*)d_in[4];
    const float* W2  = (const float*)d_in[5];
    const float* tp2 = (const float*)d_in[6];
    float* out = (float*)d_out;

    int N = in_sizes[0];      // x has N elements (N,1)
    int E = in_sizes[2];
    int nb = (N + 255) / 256;
    int eb = (E + 255) / 256;

    k_init<<<nb, 256>>>(N);
    k_w3j<<<7, 256>>>();
    k_bincount<<<eb, 256>>>(et, E);
    k_argmax<<<nb, 256>>>(N);
    k_findCo<<<eb, 256>>>(ef, et, E);
    k_findV<<<eb, 256>>>(ef, E);
    k_mids<<<64, 128>>>(x, pos, ef, et, W1, W2);
    k_final<<<1, 256>>>(pos, ef, et, tp2, out);
}